// round 14
// baseline (speedup 1.0000x reference)
#include <cuda_runtime.h>
#include <cstdint>

#define TT 32     // simulation length
#define LL 4      // number of cores
#define BB 128    // batch
#define HH 1024   // neurons/axons per core

// Spike bitmask ping-pong buffers + pair-interleaved transposed weights.
__device__ unsigned g_bitsA[BB * HH];
__device__ unsigned g_bitsB[BB * HH];
__device__ float    g_Wtp[LL * HH * HH];   // Wtp[l][a][j], j = c*64 + s*2 + k <-> n = c*64 + k*32 + s

// ---------------------------------------------------------------------------
// Spike encoding: bit-exact fp32 mirror of to_uniform_spikes.
// ---------------------------------------------------------------------------
__global__ void encode_kernel(const float* __restrict__ x, unsigned* __restrict__ U)
{
    int idx = blockIdx.x * blockDim.x + threadIdx.x;
    if (idx >= BB * HH) return;
    float xv = x[idx];
    float Nf = rintf(__fmul_rn(xv, 32.0f));
    int   N  = (int)Nf;
    unsigned bits = 0u;
    if (N >= TT) {
        bits = 0xFFFFFFFFu;
    } else if (N > 0) {
        float spacing = __fdiv_rn(32.0f, (float)N);
        float fN = (float)N;
        #pragma unroll
        for (int t = 0; t < TT; ++t) {
            float c = (float)t;
            float q = floorf(__fdiv_rn(c, spacing));
            float r = fmodf(c, spacing);         // exact remainder (matches lax.rem)
            if (q < fN && floorf(r) == 0.0f) bits |= (1u << t);
        }
    }
    U[idx] = bits;
}

// ---------------------------------------------------------------------------
// Weight transpose + pair-interleave (runs once per launch, ~12us):
//   Wtp[l][a][c*64 + s*2 + k] = W[l][c*64 + k*32 + s][a]
// so the layer kernel's (w_n0, w_n1) for axon a is ONE coalesced LDG.64.
// ---------------------------------------------------------------------------
__global__ void transpose_kernel(const float* __restrict__ W, float* __restrict__ Wtp)
{
    __shared__ float s[64][33];
    const int c  = blockIdx.x;          // 0..15  (n column group of 64)
    const int a0 = blockIdx.y * 32;     // 0..992 (a tile)
    const int l  = blockIdx.z;          // layer
    const float* Wl = W   + (size_t)l * HH * HH;
    float*       Wt = Wtp + (size_t)l * HH * HH;
    const int tx = threadIdx.x;

    #pragma unroll
    for (int i = 0; i < 8; ++i) {       // read 64 n x 32 a, coalesced along a
        int lin = tx + i * 256;
        int wn  = lin >> 5;
        int wa  = lin & 31;
        s[wn][wa] = Wl[(size_t)(c * 64 + wn) * HH + (a0 + wa)];
    }
    __syncthreads();
    #pragma unroll
    for (int i = 0; i < 8; ++i) {       // write 32 a x 64 j, coalesced along j
        int lin = tx + i * 256;
        int ar  = lin >> 6;
        int j   = lin & 63;
        int nl  = ((j & 1) << 5) | (j >> 1);   // j = s*2+k -> n_local = k*32+s
        Wt[(size_t)(a0 + ar) * HH + c * 64 + j] = s[nl][ar];
    }
}

// ---------------------------------------------------------------------------
// One layer, smem-free. CORRECTNESS-CRITICAL invariant: for every (b, n, t),
// z[t] is a SINGLE fp32 accumulator over axons a in STRICT ASCENDING order.
// Do not reassociate, split accumulators, or reorder the a loop.
//
// One warp owns one (b, ncol) unit: 64 neurons (2 chains/lane, n1 = n0+32).
// - u masks: LDG.128 (4 axons per load); weights: one coalesced LDG.64 per
//   axon from the pair-interleaved Wtp (L1-resident across same-ncol warps).
// - 1-group register prefetch; `#pragma unroll 5` (255 = 51*5) so ptxas
//   renames the rotation registers (no MOVs) and strength-reduces the
//   pointer bumps (no per-group IMAD.WIDE address chains -- R13 overhead).
// - 1024 blocks of 64 thr (2 warps) -> 98.9% SM balance; no smem, no bars.
// Plain C `if(bit) z+=w` so ptxas emits its predicate/skip-tree (R7 lesson).
// ---------------------------------------------------------------------------
#define L2F(p, off) (*reinterpret_cast<const float2*>((p) + (off)))

template<int LAST>
__global__ void __launch_bounds__(64) layer_kernel(
    const unsigned* __restrict__ Uin,
    const float*    __restrict__ Wp,       // this layer's Wtp
    const float*    __restrict__ thresholds,
    int layer,
    unsigned* __restrict__ Uout,
    float*    __restrict__ out)
{
    const int lane = threadIdx.x & 31;
    const int unit = blockIdx.x * 2 + (threadIdx.x >> 5);   // 0..2047
    const int b    = unit & 127;
    const int ncol = unit >> 7;                              // 0..15
    const float thr = thresholds[layer];

    float z0[TT], z1[TT];
    #pragma unroll
    for (int t = 0; t < TT; ++t) { z0[t] = 0.0f; z1[t] = 0.0f; }

    const uint4* __restrict__ up = reinterpret_cast<const uint4*>(Uin + b * HH);
    const float* __restrict__ p  = Wp + ncol * 64 + lane * 2;   // group 0 base

    // Prefetch group 0.
    uint4  u4 = *up++;
    float2 w0 = L2F(p, 0 * HH);
    float2 w1 = L2F(p, 1 * HH);
    float2 w2 = L2F(p, 2 * HH);
    float2 w3 = L2F(p, 3 * HH);
    p += 4 * HH;

    #define PROC(uu, ww)                                    \
        if ((uu) != 0u) {                                   \
            _Pragma("unroll")                               \
            for (int t = 0; t < TT; ++t) {                  \
                if ((uu) & (1u << t)) {                     \
                    z0[t] += (ww).x;                        \
                    z1[t] += (ww).y;                        \
                }                                           \
            }                                               \
        }

    #pragma unroll 5
    for (int g = 0; g < 255; ++g) {            // 255 = 51 * 5 (exact unroll)
        // Prefetch group g+1 (pointer-bump addressing, renamed regs).
        uint4  nu = *up++;
        float2 n0 = L2F(p, 0 * HH);
        float2 n1 = L2F(p, 1 * HH);
        float2 n2 = L2F(p, 2 * HH);
        float2 n3 = L2F(p, 3 * HH);
        p += 4 * HH;

        // Process current group: axons 4g..4g+3 in ascending order.
        PROC(u4.x, w0)
        PROC(u4.y, w1)
        PROC(u4.z, w2)
        PROC(u4.w, w3)

        u4 = nu; w0 = n0; w1 = n1; w2 = n2; w3 = n3;
    }
    // Last group (axons 1020..1023).
    PROC(u4.x, w0)
    PROC(u4.y, w1)
    PROC(u4.z, w2)
    PROC(u4.w, w3)
    #undef PROC

    // LIF recurrence over 32 cycles, all in registers (bit-exact scalar scan).
    float m0 = 0.0f, m1 = 0.0f;
    unsigned bits0 = 0u, bits1 = 0u;
    #pragma unroll
    for (int t = 0; t < TT; ++t) {
        m0 = __fadd_rn(m0, z0[t]);
        if (thr < m0) { m0 = __fsub_rn(m0, thr); bits0 |= (1u << t); }
        m1 = __fadd_rn(m1, z1[t]);
        if (thr < m1) { m1 = __fsub_rn(m1, thr); bits1 |= (1u << t); }
    }

    const int n0i = ncol * 64 + lane;        // chain 0: k=0
    const int n1i = n0i + 32;                // chain 1: k=1
    if (LAST) {
        out[b * HH + n0i] = (float)__popc(bits0) * (1.0f / 32.0f);
        out[b * HH + n1i] = (float)__popc(bits1) * (1.0f / 32.0f);
    } else {
        Uout[b * HH + n0i] = bits0;
        Uout[b * HH + n1i] = bits1;
    }
}

// ---------------------------------------------------------------------------
// Launch: encode + transpose -> 4 layer passes (ping-pong bitmask buffers).
// ---------------------------------------------------------------------------
extern "C" void kernel_launch(void* const* d_in, const int* in_sizes, int n_in,
                              void* d_out, int out_size)
{
    const float* x   = (const float*)d_in[0];                 // (128,1024)
    const float* Wts = (const float*)d_in[1];                 // (4,1024,1024)
    const float* thr = (const float*)d_in[2];                 // (4,)
    float* out = (float*)d_out;                               // (128,1024)

    static unsigned* pA = nullptr;
    static unsigned* pB = nullptr;
    static float*    pW = nullptr;
    if (!pA) {
        cudaGetSymbolAddress((void**)&pA, g_bitsA);
        cudaGetSymbolAddress((void**)&pB, g_bitsB);
        cudaGetSymbolAddress((void**)&pW, g_Wtp);
    }

    encode_kernel<<<(BB * HH + 255) / 256, 256>>>(x, pA);
    transpose_kernel<<<dim3(HH / 64, HH / 32, LL), 256>>>(Wts, pW);

    const int grid = (BB * HH / 64) / 2;      // 2048 units, 2 warps/block = 1024 blocks
    const size_t Ws = (size_t)HH * HH;

    layer_kernel<0><<<grid, 64>>>(pA, pW + 0 * Ws, thr, 0, pB, nullptr);
    layer_kernel<0><<<grid, 64>>>(pB, pW + 1 * Ws, thr, 1, pA, nullptr);
    layer_kernel<0><<<grid, 64>>>(pA, pW + 2 * Ws, thr, 2, pB, nullptr);
    layer_kernel<1><<<grid, 64>>>(pB, pW + 3 * Ws, thr, 3, nullptr, out);
}

// round 17
// speedup vs baseline: 1.0715x; 1.0715x over previous
#include <cuda_runtime.h>
#include <cstdint>

#define TT 32     // simulation length
#define LL 4      // number of cores
#define BB 128    // batch
#define HH 1024   // neurons/axons per core

// Spike bitmask ping-pong buffers + pair-interleaved transposed weights.
__device__ unsigned g_bitsA[BB * HH];
__device__ unsigned g_bitsB[BB * HH];
__device__ float    g_Wtp[LL * HH * HH];   // Wtp[l][a][j], j = c*64 + s*2 + k <-> n = c*64 + k*32 + s

// ---------------------------------------------------------------------------
// Spike encoding: bit-exact fp32 mirror of to_uniform_spikes.
// ---------------------------------------------------------------------------
__global__ void encode_kernel(const float* __restrict__ x, unsigned* __restrict__ U)
{
    int idx = blockIdx.x * blockDim.x + threadIdx.x;
    if (idx >= BB * HH) return;
    float xv = x[idx];
    float Nf = rintf(__fmul_rn(xv, 32.0f));
    int   N  = (int)Nf;
    unsigned bits = 0u;
    if (N >= TT) {
        bits = 0xFFFFFFFFu;
    } else if (N > 0) {
        float spacing = __fdiv_rn(32.0f, (float)N);
        float fN = (float)N;
        #pragma unroll
        for (int t = 0; t < TT; ++t) {
            float c = (float)t;
            float q = floorf(__fdiv_rn(c, spacing));
            float r = fmodf(c, spacing);         // exact remainder (matches lax.rem)
            if (q < fN && floorf(r) == 0.0f) bits |= (1u << t);
        }
    }
    U[idx] = bits;
}

// ---------------------------------------------------------------------------
// Weight transpose + pair-interleave (runs once per launch, ~12us):
//   Wtp[l][a][c*64 + s*2 + k] = W[l][c*64 + k*32 + s][a]
// so the layer kernel's (w_n0, w_n1) for axon a is ONE coalesced LDG.64.
// ---------------------------------------------------------------------------
__global__ void transpose_kernel(const float* __restrict__ W, float* __restrict__ Wtp)
{
    __shared__ float s[64][33];
    const int c  = blockIdx.x;          // 0..15  (n column group of 64)
    const int a0 = blockIdx.y * 32;     // 0..992 (a tile)
    const int l  = blockIdx.z;          // layer
    const float* Wl = W   + (size_t)l * HH * HH;
    float*       Wt = Wtp + (size_t)l * HH * HH;
    const int tx = threadIdx.x;

    #pragma unroll
    for (int i = 0; i < 8; ++i) {       // read 64 n x 32 a, coalesced along a
        int lin = tx + i * 256;
        int wn  = lin >> 5;
        int wa  = lin & 31;
        s[wn][wa] = Wl[(size_t)(c * 64 + wn) * HH + (a0 + wa)];
    }
    __syncthreads();
    #pragma unroll
    for (int i = 0; i < 8; ++i) {       // write 32 a x 64 j, coalesced along j
        int lin = tx + i * 256;
        int ar  = lin >> 6;
        int j   = lin & 63;
        int nl  = ((j & 1) << 5) | (j >> 1);   // j = s*2+k -> n_local = k*32+s
        Wt[(size_t)(a0 + ar) * HH + c * 64 + j] = s[nl][ar];
    }
}

// ---------------------------------------------------------------------------
// One layer, smem-free, DEPTH-2 software pipeline.
// CORRECTNESS-CRITICAL invariant: for every (b, n, t), z[t] is a SINGLE fp32
// accumulator over axons a in STRICT ASCENDING order. Do not reassociate,
// split accumulators, or reorder the a loop.
//
// One warp owns one (b, ncol) unit: 64 neurons (2 chains/lane, n1 = n0+32).
// The w stream is L2-resident (256KB/warp >> L1), so ONE group of prefetch
// (~240 cyc cover) was marginal vs L2 latency (234-262 cyc) -- R14 evidence:
// instr count fell but issue% fell with it. Holding TWO groups in flight
// (~480 cyc cover) makes the scoreboard wait resolve before use.
// 1024 blocks x 64 thr -> 98.9% SM balance; no smem, no barriers.
// Plain C `if(bit) z+=w` so ptxas emits its predicate/skip-tree (R7 lesson).
// ---------------------------------------------------------------------------
#define L2F(p, off) (*reinterpret_cast<const float2*>((p) + (off)))

template<int LAST>
__global__ void __launch_bounds__(64) layer_kernel(
    const unsigned* __restrict__ Uin,
    const float*    __restrict__ Wp,       // this layer's Wtp
    const float*    __restrict__ thresholds,
    int layer,
    unsigned* __restrict__ Uout,
    float*    __restrict__ out)
{
    const int lane = threadIdx.x & 31;
    const int unit = blockIdx.x * 2 + (threadIdx.x >> 5);   // 0..2047
    const int b    = unit & 127;
    const int ncol = unit >> 7;                              // 0..15
    const float thr = thresholds[layer];

    float z0[TT], z1[TT];
    #pragma unroll
    for (int t = 0; t < TT; ++t) { z0[t] = 0.0f; z1[t] = 0.0f; }

    const uint4* __restrict__ up = reinterpret_cast<const uint4*>(Uin + b * HH);
    const float* __restrict__ p  = Wp + ncol * 64 + lane * 2;   // group 0 base

    // Prefetch groups 0 and 1 (two groups in flight at all times).
    uint4  uA = up[0];
    float2 a0 = L2F(p, 0 * HH), a1 = L2F(p, 1 * HH);
    float2 a2 = L2F(p, 2 * HH), a3 = L2F(p, 3 * HH);
    uint4  uB = up[1];
    float2 b0 = L2F(p, 4 * HH), b1 = L2F(p, 5 * HH);
    float2 b2 = L2F(p, 6 * HH), b3 = L2F(p, 7 * HH);
    up += 2;
    p  += 8 * HH;

    #define PROC(uu, ww)                                    \
        if ((uu) != 0u) {                                   \
            _Pragma("unroll")                               \
            for (int t = 0; t < TT; ++t) {                  \
                if ((uu) & (1u << t)) {                     \
                    z0[t] += (ww).x;                        \
                    z1[t] += (ww).y;                        \
                }                                           \
            }                                               \
        }

    #pragma unroll 2
    for (int g = 0; g < 254; ++g) {            // process g, prefetch g+2
        uint4  nu = *up++;
        float2 n0 = L2F(p, 0 * HH);
        float2 n1 = L2F(p, 1 * HH);
        float2 n2 = L2F(p, 2 * HH);
        float2 n3 = L2F(p, 3 * HH);
        p += 4 * HH;

        // Process group g: axons 4g..4g+3 in ascending order.
        PROC(uA.x, a0)
        PROC(uA.y, a1)
        PROC(uA.z, a2)
        PROC(uA.w, a3)

        // Rotate: A <- B <- new (depth-2 ring).
        uA = uB; a0 = b0; a1 = b1; a2 = b2; a3 = b3;
        uB = nu; b0 = n0; b1 = n1; b2 = n2; b3 = n3;
    }
    // Drain groups 254 and 255.
    PROC(uA.x, a0)
    PROC(uA.y, a1)
    PROC(uA.z, a2)
    PROC(uA.w, a3)
    PROC(uB.x, b0)
    PROC(uB.y, b1)
    PROC(uB.z, b2)
    PROC(uB.w, b3)
    #undef PROC

    // LIF recurrence over 32 cycles, all in registers (bit-exact scalar scan).
    float m0 = 0.0f, m1 = 0.0f;
    unsigned bits0 = 0u, bits1 = 0u;
    #pragma unroll
    for (int t = 0; t < TT; ++t) {
        m0 = __fadd_rn(m0, z0[t]);
        if (thr < m0) { m0 = __fsub_rn(m0, thr); bits0 |= (1u << t); }
        m1 = __fadd_rn(m1, z1[t]);
        if (thr < m1) { m1 = __fsub_rn(m1, thr); bits1 |= (1u << t); }
    }

    const int n0i = ncol * 64 + lane;        // chain 0: k=0
    const int n1i = n0i + 32;                // chain 1: k=1
    if (LAST) {
        out[b * HH + n0i] = (float)__popc(bits0) * (1.0f / 32.0f);
        out[b * HH + n1i] = (float)__popc(bits1) * (1.0f / 32.0f);
    } else {
        Uout[b * HH + n0i] = bits0;
        Uout[b * HH + n1i] = bits1;
    }
}

// ---------------------------------------------------------------------------
// Launch: encode + transpose -> 4 layer passes (ping-pong bitmask buffers).
// ---------------------------------------------------------------------------
extern "C" void kernel_launch(void* const* d_in, const int* in_sizes, int n_in,
                              void* d_out, int out_size)
{
    const float* x   = (const float*)d_in[0];                 // (128,1024)
    const float* Wts = (const float*)d_in[1];                 // (4,1024,1024)
    const float* thr = (const float*)d_in[2];                 // (4,)
    float* out = (float*)d_out;                               // (128,1024)

    static unsigned* pA = nullptr;
    static unsigned* pB = nullptr;
    static float*    pW = nullptr;
    if (!pA) {
        cudaGetSymbolAddress((void**)&pA, g_bitsA);
        cudaGetSymbolAddress((void**)&pB, g_bitsB);
        cudaGetSymbolAddress((void**)&pW, g_Wtp);
    }

    encode_kernel<<<(BB * HH + 255) / 256, 256>>>(x, pA);
    transpose_kernel<<<dim3(HH / 64, HH / 32, LL), 256>>>(Wts, pW);

    const int grid = (BB * HH / 64) / 2;      // 2048 units, 2 warps/block = 1024 blocks
    const size_t Ws = (size_t)HH * HH;

    layer_kernel<0><<<grid, 64>>>(pA, pW + 0 * Ws, thr, 0, pB, nullptr);
    layer_kernel<0><<<grid, 64>>>(pB, pW + 1 * Ws, thr, 1, pA, nullptr);
    layer_kernel<0><<<grid, 64>>>(pA, pW + 2 * Ws, thr, 2, pB, nullptr);
    layer_kernel<1><<<grid, 64>>>(pB, pW + 3 * Ws, thr, 3, nullptr, out);
}